// round 6
// baseline (speedup 1.0000x reference)
#include <cuda_runtime.h>
#include <cuda_bf16.h>

// RGCN_317827579998 : 3-layer GraphConv, N=50000 nodes, E=800000 edges, D=128.
//
//   layer(X) = relu( (in_norm .* segsum_dst(out_norm[src] * X[src])) @ W + b )
//   (row-scaling commutes with right-mult by W and with segment-sum)
//
//   Setup (once, reused by all 3 layers): degrees -> norms -> dst-CSR.
//   Per layer: warp-per-node gather aggregation (fused norms), then
//   register-blocked SGEMM with fused bias (+ReLU).
//
// NOTE: src/dst arrive as int32 (JAX default x64-disabled downcasts the
// reference's "int64"); round-2 read them as int64 -> garbage indices -> IMA.

#define N_NODES 50000
#define N_EDGES 800000
#define D 128
#define DV (D / 4)  // float4s per row

// ---- device scratch (allocation-free requirement -> __device__ globals) ----
__device__ int   g_outdeg[N_NODES];
__device__ int   g_indeg[N_NODES];
__device__ float g_outnorm[N_NODES];
__device__ float g_innorm[N_NODES];
__device__ int   g_rowptr[N_NODES + 1];
__device__ int   g_cursor[N_NODES];
__device__ int   g_csr[N_EDGES];
__device__ float g_t[N_NODES * D];  // agg output / gemm input
__device__ float g_h[N_NODES * D];  // layer output (ping buffer)

// ---------------------------------------------------------------------------
__global__ void k_zero_deg() {
    int i = blockIdx.x * blockDim.x + threadIdx.x;
    if (i < N_NODES) {
        g_outdeg[i] = 0;
        g_indeg[i]  = 0;
    }
}

__global__ void k_deg(const int* __restrict__ src,
                      const int* __restrict__ dst) {
    int e = blockIdx.x * blockDim.x + threadIdx.x;
    if (e < N_EDGES) {
        unsigned s = (unsigned)src[e];
        unsigned d = (unsigned)dst[e];
        if (s < N_NODES) atomicAdd(&g_outdeg[s], 1);
        if (d < N_NODES) atomicAdd(&g_indeg[d], 1);
    }
}

__global__ void k_norm() {
    int i = blockIdx.x * blockDim.x + threadIdx.x;
    if (i < N_NODES) {
        g_outnorm[i] = rsqrtf(fmaxf((float)g_outdeg[i], 1.0f));
        g_innorm[i]  = rsqrtf(fmaxf((float)g_indeg[i], 1.0f));
    }
}

// single-block exclusive scan of g_indeg -> g_rowptr (+ copy into g_cursor)
__global__ void k_scan() {
    __shared__ int sdata[1024];
    __shared__ int s_carry;
    int t = threadIdx.x;
    if (t == 0) s_carry = 0;
    __syncthreads();

    for (int base = 0; base < N_NODES; base += 1024) {
        int i = base + t;
        int v = (i < N_NODES) ? g_indeg[i] : 0;
        sdata[t] = v;
        __syncthreads();
        #pragma unroll
        for (int off = 1; off < 1024; off <<= 1) {
            int x = (t >= off) ? sdata[t - off] : 0;
            __syncthreads();
            sdata[t] += x;
            __syncthreads();
        }
        int carry = s_carry;
        int excl  = sdata[t] - v;
        if (i < N_NODES) {
            int rp = carry + excl;
            g_rowptr[i] = rp;
            g_cursor[i] = rp;
        }
        __syncthreads();
        if (t == 0) s_carry = carry + sdata[1023];
        __syncthreads();
    }
    if (t == 0) g_rowptr[N_NODES] = s_carry;
}

__global__ void k_fill(const int* __restrict__ src,
                       const int* __restrict__ dst) {
    int e = blockIdx.x * blockDim.x + threadIdx.x;
    if (e < N_EDGES) {
        unsigned s = (unsigned)src[e];
        unsigned d = (unsigned)dst[e];
        if (s < N_NODES && d < N_NODES) {
            int pos = atomicAdd(&g_cursor[d], 1);
            g_csr[pos] = (int)s;
        }
    }
}

// ---------------------------------------------------------------------------
// Aggregation: one warp per node. T[v] = in_norm[v] * sum_e out_norm[s] * X[s]
__global__ void k_agg(const float* __restrict__ X, float* __restrict__ T) {
    int warp = (blockIdx.x * blockDim.x + threadIdx.x) >> 5;
    if (warp >= N_NODES) return;
    int lane = threadIdx.x & 31;

    int beg = g_rowptr[warp];
    int end = g_rowptr[warp + 1];

    const float4* X4 = (const float4*)X;
    float4 acc = make_float4(0.f, 0.f, 0.f, 0.f);

    for (int i = beg; i < end; i++) {
        int   s  = g_csr[i];
        float on = __ldg(&g_outnorm[s]);
        float4 xv = X4[s * DV + lane];
        acc.x += xv.x * on;
        acc.y += xv.y * on;
        acc.z += xv.z * on;
        acc.w += xv.w * on;
    }
    float inn = g_innorm[warp];
    acc.x *= inn; acc.y *= inn; acc.z *= inn; acc.w *= inn;
    ((float4*)T)[warp * DV + lane] = acc;
}

// ---------------------------------------------------------------------------
// SGEMM: C[M,128] = A[M,128] @ W[128,128] + b (+ReLU)
// BM=64, BN=128, BK=8, TM=8, TN=8, 128 threads/block
template <bool RELU>
__global__ void __launch_bounds__(128)
k_gemm(const float* __restrict__ A, const float* __restrict__ W,
       const float* __restrict__ b, float* __restrict__ C, int M) {
    __shared__ float As[8][64];
    __shared__ float Bs[8][128];

    int tid = threadIdx.x;
    int blockRow = blockIdx.x;  // tile of 64 rows

    int rowA = tid >> 1;          // 0..63
    int colA = (tid & 1) * 4;     // 0 or 4
    int rowB = tid >> 4;          // 0..7
    int colB = (tid & 15) * 4;    // 0..60  (second chunk at +64)
    int tRow = (tid >> 4) * 8;    // 0..56
    int tCol = (tid & 15) * 8;    // 0..120

    int aRow = blockRow * 64 + rowA;
    bool aValid = (aRow < M);

    float acc[8][8];
    #pragma unroll
    for (int i = 0; i < 8; i++)
        #pragma unroll
        for (int j = 0; j < 8; j++) acc[i][j] = 0.f;

    for (int kc = 0; kc < D; kc += 8) {
        float4 av = aValid ? *(const float4*)(A + (size_t)aRow * D + kc + colA)
                           : make_float4(0.f, 0.f, 0.f, 0.f);
        As[colA + 0][rowA] = av.x;
        As[colA + 1][rowA] = av.y;
        As[colA + 2][rowA] = av.z;
        As[colA + 3][rowA] = av.w;

        *(float4*)&Bs[rowB][colB]      = *(const float4*)(W + (kc + rowB) * D + colB);
        *(float4*)&Bs[rowB][colB + 64] = *(const float4*)(W + (kc + rowB) * D + colB + 64);
        __syncthreads();

        #pragma unroll
        for (int k = 0; k < 8; k++) {
            float regM[8], regN[8];
            float4 m0 = *(const float4*)&As[k][tRow];
            float4 m1 = *(const float4*)&As[k][tRow + 4];
            regM[0] = m0.x; regM[1] = m0.y; regM[2] = m0.z; regM[3] = m0.w;
            regM[4] = m1.x; regM[5] = m1.y; regM[6] = m1.z; regM[7] = m1.w;
            float4 n0 = *(const float4*)&Bs[k][tCol];
            float4 n1 = *(const float4*)&Bs[k][tCol + 4];
            regN[0] = n0.x; regN[1] = n0.y; regN[2] = n0.z; regN[3] = n0.w;
            regN[4] = n1.x; regN[5] = n1.y; regN[6] = n1.z; regN[7] = n1.w;
            #pragma unroll
            for (int i = 0; i < 8; i++)
                #pragma unroll
                for (int j = 0; j < 8; j++)
                    acc[i][j] += regM[i] * regN[j];
        }
        __syncthreads();
    }

    float bias[8];
    #pragma unroll
    for (int j = 0; j < 8; j++) bias[j] = b[tCol + j];

    #pragma unroll
    for (int i = 0; i < 8; i++) {
        int r = blockRow * 64 + tRow + i;
        if (r < M) {
            float4 o0, o1;
            float v;
            v = acc[i][0] + bias[0]; o0.x = RELU ? fmaxf(v, 0.f) : v;
            v = acc[i][1] + bias[1]; o0.y = RELU ? fmaxf(v, 0.f) : v;
            v = acc[i][2] + bias[2]; o0.z = RELU ? fmaxf(v, 0.f) : v;
            v = acc[i][3] + bias[3]; o0.w = RELU ? fmaxf(v, 0.f) : v;
            v = acc[i][4] + bias[4]; o1.x = RELU ? fmaxf(v, 0.f) : v;
            v = acc[i][5] + bias[5]; o1.y = RELU ? fmaxf(v, 0.f) : v;
            v = acc[i][6] + bias[6]; o1.z = RELU ? fmaxf(v, 0.f) : v;
            v = acc[i][7] + bias[7]; o1.w = RELU ? fmaxf(v, 0.f) : v;
            *(float4*)(C + (size_t)r * D + tCol)     = o0;
            *(float4*)(C + (size_t)r * D + tCol + 4) = o1;
        }
    }
}

// ---------------------------------------------------------------------------
extern "C" void kernel_launch(void* const* d_in, const int* in_sizes, int n_in,
                              void* d_out, int out_size) {
    const float* x   = (const float*)d_in[0];
    const int*   src = (const int*)d_in[1];   // int32 (JAX x64 disabled)
    const int*   dst = (const int*)d_in[2];
    const float* W1  = (const float*)d_in[3];
    const float* b1  = (const float*)d_in[4];
    const float* W2  = (const float*)d_in[5];
    const float* b2  = (const float*)d_in[6];
    const float* W3  = (const float*)d_in[7];
    const float* b3  = (const float*)d_in[8];
    float* out = (float*)d_out;

    const int nodeBlocks = (N_NODES + 255) / 256;      // 196
    const int edgeBlocks = (N_EDGES + 255) / 256;      // 3125
    const int aggBlocks  = (N_NODES * 32 + 255) / 256; // 6250 (warp/node)
    const int gemmBlocks = (N_NODES + 63) / 64;        // 782

    // setup: degrees, norms, CSR (shared by all 3 layers)
    k_zero_deg<<<nodeBlocks, 256>>>();
    k_deg<<<edgeBlocks, 256>>>(src, dst);
    k_norm<<<nodeBlocks, 256>>>();
    k_scan<<<1, 1024>>>();
    k_fill<<<edgeBlocks, 256>>>(src, dst);

    // layer 1
    k_agg<<<aggBlocks, 256>>>(x, g_t);
    k_gemm<true><<<gemmBlocks, 128>>>(g_t, W1, b1, g_h, N_NODES);
    // layer 2
    k_agg<<<aggBlocks, 256>>>(g_h, g_t);
    k_gemm<true><<<gemmBlocks, 128>>>(g_t, W2, b2, g_h, N_NODES);
    // layer 3 (no ReLU) -> d_out
    k_agg<<<aggBlocks, 256>>>(g_h, g_t);
    k_gemm<false><<<gemmBlocks, 128>>>(g_t, W3, b3, out, N_NODES);
}

// round 11
// speedup vs baseline: 1.0014x; 1.0014x over previous
#include <cuda_runtime.h>
#include <cuda_bf16.h>

// RGCN_317827579998 : 3-layer GraphConv, N=50000 nodes, E=800000 edges, D=128.
//
//   layer(X) = relu( (in_norm .* segsum_dst(out_norm[src] * X[src])) @ W + b )
//   (row-scaling commutes with right-mult by W and with segment-sum)
//
// R10 = known-good R4 kernel + ONE change: the aggregation edge loop is
// unrolled x8 with batched independent loads (indices, then norms+rows),
// raising MLP from ~1-2 to ~8-16 to hide L2 latency. Everything else is
// byte-identical to the R4 kernel that passed at 5363us / rel_err 2.4e-7.

#define N_NODES 50000
#define N_EDGES 800000
#define D 128
#define DV (D / 4)  // float4s per row

// ---- device scratch (allocation-free requirement -> __device__ globals) ----
__device__ int   g_outdeg[N_NODES];
__device__ int   g_indeg[N_NODES];
__device__ float g_outnorm[N_NODES];
__device__ float g_innorm[N_NODES];
__device__ int   g_rowptr[N_NODES + 1];
__device__ int   g_cursor[N_NODES];
__device__ int   g_csr[N_EDGES];
__device__ float g_t[N_NODES * D];  // agg output / gemm input
__device__ float g_h[N_NODES * D];  // layer output (ping buffer)

// ---------------------------------------------------------------------------
__global__ void k_zero_deg() {
    int i = blockIdx.x * blockDim.x + threadIdx.x;
    if (i < N_NODES) {
        g_outdeg[i] = 0;
        g_indeg[i]  = 0;
    }
}

__global__ void k_deg(const int* __restrict__ src,
                      const int* __restrict__ dst) {
    int e = blockIdx.x * blockDim.x + threadIdx.x;
    if (e < N_EDGES) {
        unsigned s = (unsigned)src[e];
        unsigned d = (unsigned)dst[e];
        if (s < N_NODES) atomicAdd(&g_outdeg[s], 1);
        if (d < N_NODES) atomicAdd(&g_indeg[d], 1);
    }
}

__global__ void k_norm() {
    int i = blockIdx.x * blockDim.x + threadIdx.x;
    if (i < N_NODES) {
        g_outnorm[i] = rsqrtf(fmaxf((float)g_outdeg[i], 1.0f));
        g_innorm[i]  = rsqrtf(fmaxf((float)g_indeg[i], 1.0f));
    }
}

// single-block exclusive scan of g_indeg -> g_rowptr (+ copy into g_cursor)
__global__ void k_scan() {
    __shared__ int sdata[1024];
    __shared__ int s_carry;
    int t = threadIdx.x;
    if (t == 0) s_carry = 0;
    __syncthreads();

    for (int base = 0; base < N_NODES; base += 1024) {
        int i = base + t;
        int v = (i < N_NODES) ? g_indeg[i] : 0;
        sdata[t] = v;
        __syncthreads();
        #pragma unroll
        for (int off = 1; off < 1024; off <<= 1) {
            int x = (t >= off) ? sdata[t - off] : 0;
            __syncthreads();
            sdata[t] += x;
            __syncthreads();
        }
        int carry = s_carry;
        int excl  = sdata[t] - v;
        if (i < N_NODES) {
            int rp = carry + excl;
            g_rowptr[i] = rp;
            g_cursor[i] = rp;
        }
        __syncthreads();
        if (t == 0) s_carry = carry + sdata[1023];
        __syncthreads();
    }
    if (t == 0) g_rowptr[N_NODES] = s_carry;
}

__global__ void k_fill(const int* __restrict__ src,
                       const int* __restrict__ dst) {
    int e = blockIdx.x * blockDim.x + threadIdx.x;
    if (e < N_EDGES) {
        unsigned s = (unsigned)src[e];
        unsigned d = (unsigned)dst[e];
        if (s < N_NODES && d < N_NODES) {
            int pos = atomicAdd(&g_cursor[d], 1);
            g_csr[pos] = (int)s;
        }
    }
}

// ---------------------------------------------------------------------------
// Aggregation: one warp per node. T[v] = in_norm[v] * sum_e out_norm[s] * X[s]
// Edge loop unrolled x8: 8 independent index loads, then 8 norm + 8 row loads
// issued back-to-back (MLP ~8-16) before any dependent FMA.
__global__ void k_agg(const float* __restrict__ X, float* __restrict__ T) {
    int node = (blockIdx.x * blockDim.x + threadIdx.x) >> 5;
    if (node >= N_NODES) return;
    int lane = threadIdx.x & 31;

    int beg = g_rowptr[node];
    int end = g_rowptr[node + 1];

    const float4* X4 = (const float4*)X;
    float4 acc = make_float4(0.f, 0.f, 0.f, 0.f);

    int i = beg;
    for (; i + 8 <= end; i += 8) {
        int s0 = g_csr[i + 0];
        int s1 = g_csr[i + 1];
        int s2 = g_csr[i + 2];
        int s3 = g_csr[i + 3];
        int s4 = g_csr[i + 4];
        int s5 = g_csr[i + 5];
        int s6 = g_csr[i + 6];
        int s7 = g_csr[i + 7];
        float n0 = __ldg(&g_outnorm[s0]);
        float n1 = __ldg(&g_outnorm[s1]);
        float n2 = __ldg(&g_outnorm[s2]);
        float n3 = __ldg(&g_outnorm[s3]);
        float n4 = __ldg(&g_outnorm[s4]);
        float n5 = __ldg(&g_outnorm[s5]);
        float n6 = __ldg(&g_outnorm[s6]);
        float n7 = __ldg(&g_outnorm[s7]);
        float4 a0 = X4[s0 * DV + lane];
        float4 a1 = X4[s1 * DV + lane];
        float4 a2 = X4[s2 * DV + lane];
        float4 a3 = X4[s3 * DV + lane];
        float4 a4 = X4[s4 * DV + lane];
        float4 a5 = X4[s5 * DV + lane];
        float4 a6 = X4[s6 * DV + lane];
        float4 a7 = X4[s7 * DV + lane];
        acc.x += a0.x * n0 + a1.x * n1 + a2.x * n2 + a3.x * n3
               + a4.x * n4 + a5.x * n5 + a6.x * n6 + a7.x * n7;
        acc.y += a0.y * n0 + a1.y * n1 + a2.y * n2 + a3.y * n3
               + a4.y * n4 + a5.y * n5 + a6.y * n6 + a7.y * n7;
        acc.z += a0.z * n0 + a1.z * n1 + a2.z * n2 + a3.z * n3
               + a4.z * n4 + a5.z * n5 + a6.z * n6 + a7.z * n7;
        acc.w += a0.w * n0 + a1.w * n1 + a2.w * n2 + a3.w * n3
               + a4.w * n4 + a5.w * n5 + a6.w * n6 + a7.w * n7;
    }
    for (; i < end; i++) {
        int   s  = g_csr[i];
        float on = __ldg(&g_outnorm[s]);
        float4 xv = X4[s * DV + lane];
        acc.x += xv.x * on;
        acc.y += xv.y * on;
        acc.z += xv.z * on;
        acc.w += xv.w * on;
    }
    float inn = g_innorm[node];
    acc.x *= inn; acc.y *= inn; acc.z *= inn; acc.w *= inn;
    ((float4*)T)[node * DV + lane] = acc;
}

// ---------------------------------------------------------------------------
// SGEMM: C[M,128] = A[M,128] @ W[128,128] + b (+ReLU)
// BM=64, BN=128, BK=8, TM=8, TN=8, 128 threads/block  (unchanged from R4)
template <bool RELU>
__global__ void __launch_bounds__(128)
k_gemm(const float* __restrict__ A, const float* __restrict__ W,
       const float* __restrict__ b, float* __restrict__ C, int M) {
    __shared__ float As[8][64];
    __shared__ float Bs[8][128];

    int tid = threadIdx.x;
    int blockRow = blockIdx.x;  // tile of 64 rows

    int rowA = tid >> 1;          // 0..63
    int colA = (tid & 1) * 4;     // 0 or 4
    int rowB = tid >> 4;          // 0..7
    int colB = (tid & 15) * 4;    // 0..60  (second chunk at +64)
    int tRow = (tid >> 4) * 8;    // 0..56
    int tCol = (tid & 15) * 8;    // 0..120

    int aRow = blockRow * 64 + rowA;
    bool aValid = (aRow < M);

    float acc[8][8];
    #pragma unroll
    for (int i = 0; i < 8; i++)
        #pragma unroll
        for (int j = 0; j < 8; j++) acc[i][j] = 0.f;

    for (int kc = 0; kc < D; kc += 8) {
        float4 av = aValid ? *(const float4*)(A + (size_t)aRow * D + kc + colA)
                           : make_float4(0.f, 0.f, 0.f, 0.f);
        As[colA + 0][rowA] = av.x;
        As[colA + 1][rowA] = av.y;
        As[colA + 2][rowA] = av.z;
        As[colA + 3][rowA] = av.w;

        *(float4*)&Bs[rowB][colB]      = *(const float4*)(W + (kc + rowB) * D + colB);
        *(float4*)&Bs[rowB][colB + 64] = *(const float4*)(W + (kc + rowB) * D + colB + 64);
        __syncthreads();

        #pragma unroll
        for (int k = 0; k < 8; k++) {
            float regM[8], regN[8];
            float4 m0 = *(const float4*)&As[k][tRow];
            float4 m1 = *(const float4*)&As[k][tRow + 4];
            regM[0] = m0.x; regM[1] = m0.y; regM[2] = m0.z; regM[3] = m0.w;
            regM[4] = m1.x; regM[5] = m1.y; regM[6] = m1.z; regM[7] = m1.w;
            float4 n0 = *(const float4*)&Bs[k][tCol];
            float4 n1 = *(const float4*)&Bs[k][tCol + 4];
            regN[0] = n0.x; regN[1] = n0.y; regN[2] = n0.z; regN[3] = n0.w;
            regN[4] = n1.x; regN[5] = n1.y; regN[6] = n1.z; regN[7] = n1.w;
            #pragma unroll
            for (int i = 0; i < 8; i++)
                #pragma unroll
                for (int j = 0; j < 8; j++)
                    acc[i][j] += regM[i] * regN[j];
        }
        __syncthreads();
    }

    float bias[8];
    #pragma unroll
    for (int j = 0; j < 8; j++) bias[j] = b[tCol + j];

    #pragma unroll
    for (int i = 0; i < 8; i++) {
        int r = blockRow * 64 + tRow + i;
        if (r < M) {
            float4 o0, o1;
            float v;
            v = acc[i][0] + bias[0]; o0.x = RELU ? fmaxf(v, 0.f) : v;
            v = acc[i][1] + bias[1]; o0.y = RELU ? fmaxf(v, 0.f) : v;
            v = acc[i][2] + bias[2]; o0.z = RELU ? fmaxf(v, 0.f) : v;
            v = acc[i][3] + bias[3]; o0.w = RELU ? fmaxf(v, 0.f) : v;
            v = acc[i][4] + bias[4]; o1.x = RELU ? fmaxf(v, 0.f) : v;
            v = acc[i][5] + bias[5]; o1.y = RELU ? fmaxf(v, 0.f) : v;
            v = acc[i][6] + bias[6]; o1.z = RELU ? fmaxf(v, 0.f) : v;
            v = acc[i][7] + bias[7]; o1.w = RELU ? fmaxf(v, 0.f) : v;
            *(float4*)(C + (size_t)r * D + tCol)     = o0;
            *(float4*)(C + (size_t)r * D + tCol + 4) = o1;
        }
    }
}

// ---------------------------------------------------------------------------
extern "C" void kernel_launch(void* const* d_in, const int* in_sizes, int n_in,
                              void* d_out, int out_size) {
    const float* x   = (const float*)d_in[0];
    const int*   src = (const int*)d_in[1];   // int32 (JAX x64 disabled)
    const int*   dst = (const int*)d_in[2];
    const float* W1  = (const float*)d_in[3];
    const float* b1  = (const float*)d_in[4];
    const float* W2  = (const float*)d_in[5];
    const float* b2  = (const float*)d_in[6];
    const float* W3  = (const float*)d_in[7];
    const float* b3  = (const float*)d_in[8];
    float* out = (float*)d_out;

    const int nodeBlocks = (N_NODES + 255) / 256;      // 196
    const int edgeBlocks = (N_EDGES + 255) / 256;      // 3125
    const int aggBlocks  = (N_NODES * 32 + 255) / 256; // 6250 (warp/node)
    const int gemmBlocks = (N_NODES + 63) / 64;        // 782

    // setup: degrees, norms, CSR (shared by all 3 layers)
    k_zero_deg<<<nodeBlocks, 256>>>();
    k_deg<<<edgeBlocks, 256>>>(src, dst);
    k_norm<<<nodeBlocks, 256>>>();
    k_scan<<<1, 1024>>>();
    k_fill<<<edgeBlocks, 256>>>(src, dst);

    // layer 1
    k_agg<<<aggBlocks, 256>>>(x, g_t);
    k_gemm<true><<<gemmBlocks, 128>>>(g_t, W1, b1, g_h, N_NODES);
    // layer 2
    k_agg<<<aggBlocks, 256>>>(g_h, g_t);
    k_gemm<true><<<gemmBlocks, 128>>>(g_t, W2, b2, g_h, N_NODES);
    // layer 3 (no ReLU) -> d_out
    k_agg<<<aggBlocks, 256>>>(g_h, g_t);
    k_gemm<false><<<gemmBlocks, 128>>>(g_t, W3, b3, out, N_NODES);
}